// round 14
// baseline (speedup 1.0000x reference)
#include <cuda_runtime.h>
#include <cuda_fp16.h>
#include <mma.h>
#include <cstdint>

using namespace nvcuda;

#define BATCH 64
#define T_LEN 512
#define F_IN  132
#define F_PAD 192
#define HID   1024
#define G4    4096

#define N_BLOCKS 96

// ---------------- device global scratch ----------------
__device__ __half g_W5[5ULL * G4 * HID];              // Whh1, Wih2, Whh2, Wih3, Whh3
__device__ __half g_Wih1p[G4 * F_PAD];                // Wih1 padded 132->192
__device__ __half g_W1d[(size_t)G4 * HID];            // Wih1 @ Wd  (teacher-forcing fold)
__device__ __half g_Wdp[144 * HID];                   // Wd padded 132->144 rows
__device__ __half g_frames[(size_t)T_LEN * BATCH * F_PAD];
__device__ __half g_h2hist[(size_t)T_LEN * BATCH * HID];
__device__ __half g_h[2][3][BATCH][HID];              // ping-pong hidden states
__device__ float  g_c[3][BATCH][HID];                 // cell states fp32
__device__ float  g_b1f1[G4], g_b1f0[G4], g_b2[G4], g_b3[G4];

// grid barrier state (zero-initialized; sense-reversing, safe across replays)
__device__ unsigned g_gb_count;
__device__ unsigned g_gb_phase;

// ---------------- helpers ----------------
__device__ __forceinline__ void cp16(void* s, const void* g) {
    unsigned sa = (unsigned)__cvta_generic_to_shared(s);
    asm volatile("cp.async.cg.shared.global [%0], [%1], 16;\n" :: "r"(sa), "l"(g));
}
__device__ __forceinline__ void cp_commit() { asm volatile("cp.async.commit_group;\n"); }
__device__ __forceinline__ void cp_wait0()  { asm volatile("cp.async.wait_group 0;\n"); }
__device__ __forceinline__ void cp_wait1()  { asm volatile("cp.async.wait_group 1;\n"); }
__device__ __forceinline__ void wg_bar(int g) {
    asm volatile("bar.sync %0, 128;\n" :: "r"(1 + g) : "memory");
}
// hardware tanh (MUFU.TANH); sigmoid via exact identity 0.5*tanh(x/2)+0.5
__device__ __forceinline__ float fast_tanh(float x) {
    float y;
    asm("tanh.approx.f32 %0, %1;" : "=f"(y) : "f"(x));
    return y;
}
__device__ __forceinline__ float fast_sigmoid(float x) {
    return fmaf(0.5f, fast_tanh(0.5f * x), 0.5f);
}

// ---------------- fused setup kernel #1 ----------------
__global__ void k_setup(const float* __restrict__ Whh1, const float* __restrict__ Wih2,
                        const float* __restrict__ Whh2, const float* __restrict__ Wih3,
                        const float* __restrict__ Whh3, const float* __restrict__ Wih1,
                        const float* __restrict__ Wd,   const float* __restrict__ rs) {
    const size_t M  = (size_t)G4 * HID;
    const size_t N0 = 5 * M;
    const size_t N1 = (size_t)G4 * F_PAD;
    const size_t N2 = (size_t)144 * HID;
    const size_t N3 = (size_t)T_LEN * BATCH * F_PAD;
    const size_t N4 = 2ULL * 3 * BATCH * HID;
    const size_t N5 = 3ULL * BATCH * HID;
    const size_t T0 = N0, T1 = T0 + N1, T2 = T1 + N2, T3 = T2 + N3, T4 = T3 + N4,
                 T5 = T4 + N5;
    for (size_t i = (size_t)blockIdx.x * blockDim.x + threadIdx.x; i < T5;
         i += (size_t)gridDim.x * blockDim.x) {
        if (i < T0) {
            size_t m = i / M, r = i % M;
            const float* src = (m == 0) ? Whh1 : (m == 1) ? Wih2 : (m == 2) ? Whh2
                              : (m == 3) ? Wih3 : Whh3;
            g_W5[i] = __float2half_rn(src[r]);
        } else if (i < T1) {
            size_t j = i - T0;
            int c = (int)(j % F_PAD), r = (int)(j / F_PAD);
            g_Wih1p[j] = __float2half_rn(c < F_IN ? Wih1[(size_t)r * F_IN + c] : 0.f);
        } else if (i < T2) {
            size_t j = i - T1;
            int k = (int)(j % HID), r = (int)(j / HID);
            g_Wdp[j] = __float2half_rn(r < F_IN ? Wd[(size_t)r * HID + k] : 0.f);
        } else if (i < T3) {
            size_t j = i - T2;
            int c = (int)(j % F_PAD);
            size_t rem = j / F_PAD;
            int b = (int)(rem % BATCH), t = (int)(rem / BATCH);
            g_frames[j] = __float2half_rn(
                c < F_IN ? rs[((size_t)b * T_LEN + t) * F_IN + c] : 0.f);
        } else if (i < T4) {
            (&g_h[0][0][0][0])[i - T3] = __float2half_rn(0.f);
        } else {
            (&g_c[0][0][0])[i - T4] = 0.f;
        }
    }
}

// ---------------- setup kernel #2: W1d = Wih1 @ Wd ----------------
__global__ void __launch_bounds__(256) k_w1d(const float* __restrict__ Wih1,
                                             const float* __restrict__ Wd) {
    __shared__ float ws[64][133];
    int jb = blockIdx.y * 64, kb = blockIdx.x * 64;
    for (int idx = threadIdx.x; idx < 64 * F_IN; idx += 256) {
        int r = idx / F_IN, c = idx % F_IN;
        ws[r][c] = Wih1[(size_t)(jb + r) * F_IN + c];
    }
    __syncthreads();
    int tx = threadIdx.x & 15, ty = threadIdx.x >> 4;
    float acc[4][4] = {};
    const float* wdp = Wd + kb + tx * 4;
    for (int f = 0; f < F_IN; f++) {
        float4 d = *(const float4*)(wdp + (size_t)f * HID);
        float a0 = ws[ty * 4 + 0][f], a1 = ws[ty * 4 + 1][f];
        float a2 = ws[ty * 4 + 2][f], a3 = ws[ty * 4 + 3][f];
        acc[0][0] += a0 * d.x; acc[0][1] += a0 * d.y; acc[0][2] += a0 * d.z; acc[0][3] += a0 * d.w;
        acc[1][0] += a1 * d.x; acc[1][1] += a1 * d.y; acc[1][2] += a1 * d.z; acc[1][3] += a1 * d.w;
        acc[2][0] += a2 * d.x; acc[2][1] += a2 * d.y; acc[2][2] += a2 * d.z; acc[2][3] += a2 * d.w;
        acc[3][0] += a3 * d.x; acc[3][1] += a3 * d.y; acc[3][2] += a3 * d.z; acc[3][3] += a3 * d.w;
    }
    #pragma unroll
    for (int jj = 0; jj < 4; jj++) {
        int j = jb + ty * 4 + jj;
        #pragma unroll
        for (int kk = 0; kk < 4; kk++)
            g_W1d[(size_t)j * HID + kb + tx * 4 + kk] = __float2half_rn(acc[jj][kk]);
    }
}

// ---------------- setup kernel #3: biases ----------------
__global__ void k_bias(const float* __restrict__ bih1, const float* __restrict__ bhh1,
                       const float* __restrict__ bih2, const float* __restrict__ bhh2,
                       const float* __restrict__ bih3, const float* __restrict__ bhh3,
                       const float* __restrict__ Wih1, const float* __restrict__ bd) {
    int j = blockIdx.x * blockDim.x + threadIdx.x;
    if (j >= G4) return;
    float b1 = bih1[j] + bhh1[j];
    float acc = 0.f;
    for (int f = 0; f < F_IN; f++) acc += Wih1[(size_t)j * F_IN + f] * bd[f];
    g_b1f1[j] = b1;
    g_b1f0[j] = b1 + acc;
    g_b2[j] = bih2[j] + bhh2[j];
    g_b3[j] = bih3[j] + bhh3[j];
}

// ---------------- persistent recurrence kernel ----------------
// 96 blocks x 512 threads, 1 block/SM. Block = cell (bx>>5) x 32 hidden cols
// (128 gate rows). 4 warpgroups split K 4 ways (WG g owns chunks 4j+g).
// K-chunk = 32 with a PRIVATE 3-stage ring per WG -> 2 chunks in flight
// (chunk j+2 issued at iter j), hiding L2 fetch latency fully.
struct Seg { const __half* a; int lda; const __half* w; int ldw; int nch; };

#define KC      32
#define ROWLEN  40                        // 32 + 8 pad halves (80B row)
#define W_STG   (128 * ROWLEN * 2)        // 10240
#define A_STG   (64 * ROWLEN * 2)         // 5120
#define N_STAGES 3
#define W_REGION (4 * N_STAGES * W_STG)   // 122880
#define SMEM_P  (W_REGION + 4 * N_STAGES * A_STG) // 184320
#define GS_BYTES 34816                    // 64 x 136 floats

__device__ __forceinline__ void grid_barrier() {
    __syncthreads();
    if (threadIdx.x == 0) {
        unsigned snap = *(volatile unsigned*)&g_gb_phase;
        __threadfence();
        unsigned old = atomicAdd(&g_gb_count, 1);
        if (old == N_BLOCKS - 1) {
            atomicExch(&g_gb_count, 0);
            __threadfence();
            atomicAdd(&g_gb_phase, 1);
        } else {
            while (*(volatile unsigned*)&g_gb_phase == snap) __nanosleep(64);
        }
        __threadfence();
    }
    __syncthreads();
}

__global__ void __launch_bounds__(512, 1) k_persist() {
    extern __shared__ __align__(16) unsigned char dsm[];

    const int tid  = threadIdx.x;
    const int warp = tid >> 5;
    const int g    = warp >> 2;          // warpgroup 0..3: K residue class
    const int wc   = warp & 3;           // gate-col quarter (32 cols)
    const int wtid = tid & 127;
    const int cell = blockIdx.x >> 5;
    const int h_base = (blockIdx.x & 31) << 5;   // 32 hidden cols

    const size_t M = (size_t)G4 * HID;

    auto Wstage = [&](int st) -> __half* {
        return (__half*)(dsm + (size_t)(g * N_STAGES + st) * W_STG);
    };
    auto Astage = [&](int st) -> __half* {
        return (__half*)(dsm + W_REGION + (size_t)(g * N_STAGES + st) * A_STG);
    };

    auto segs = [&](int t, Seg& s0, Seg& s1) {
        int pin = t & 1;
        int flag = ((t % 10) < 5) ? 1 : 0;
        const __half* hin = &g_h[pin][0][0][0];
        const __half* h0 = hin;
        const __half* h1 = hin + BATCH * HID;
        const __half* h2 = hin + 2 * BATCH * HID;
        if (cell == 0) {
            if (flag) s0 = { g_frames + (size_t)t * BATCH * F_PAD, F_PAD, g_Wih1p, F_PAD, F_PAD / KC };
            else      s0 = { h2, HID, g_W1d, HID, HID / KC };
            s1 = { h0, HID, g_W5, HID, HID / KC };
        } else if (cell == 1) {
            s0 = { h0, HID, g_W5 + 1 * M, HID, HID / KC };
            s1 = { h1, HID, g_W5 + 2 * M, HID, HID / KC };
        } else {
            s0 = { h1, HID, g_W5 + 3 * M, HID, HID / KC };
            s1 = { h2, HID, g_W5 + 4 * M, HID, HID / KC };
        }
    };

    // chunk ci (32-wide); W tile 128 rows x 32 cols = 512 cp16, 4/thread (wg)
    auto loadW = [&](const Seg& s0, const Seg& s1, int ci, int st) {
        const Seg& sg = (ci < s0.nch) ? s0 : s1;
        int k0 = ((ci < s0.nch) ? ci : ci - s0.nch) * KC;
        __half* W = Wstage(st);
        #pragma unroll
        for (int p = 0; p < 4; p++) {
            int idx = p * 128 + wtid;
            int r = idx >> 2, c4 = idx & 3;
            int grow = ((r >> 5) << 10) + h_base + (r & 31);
            cp16(W + r * ROWLEN + c4 * 8, sg.w + (size_t)grow * sg.ldw + k0 + c4 * 8);
        }
    };
    // A tile 64 rows x 32 cols = 256 cp16, 2/thread (wg)
    auto loadA = [&](const Seg& s0, const Seg& s1, int ci, int st) {
        const Seg& sg = (ci < s0.nch) ? s0 : s1;
        int k0 = ((ci < s0.nch) ? ci : ci - s0.nch) * KC;
        __half* A = Astage(st);
        #pragma unroll
        for (int p = 0; p < 2; p++) {
            int idx = p * 128 + wtid;
            int r = idx >> 2, c4 = idx & 3;
            cp16(A + r * ROWLEN + c4 * 8, sg.a + (size_t)r * sg.lda + k0 + c4 * 8);
        }
    };

    // t=0 prologue: WG's first two chunks (g, 4+g) into stages 0,1
    {
        Seg s0, s1; segs(0, s0, s1);
        loadW(s0, s1, g, 0); loadA(s0, s1, g, 0); cp_commit();
        loadW(s0, s1, 4 + g, 1); loadA(s0, s1, 4 + g, 1); cp_commit();
    }

    for (int t = 0; t < T_LEN; t++) {
        Seg s0, s1; segs(t, s0, s1);
        const int nch = s0.nch + s1.nch;            // 38 or 64
        const int nIter = (nch - g + 3) >> 2;       // this WG's chunk count

        wmma::fragment<wmma::accumulator, 16, 16, 16, float> acc[4][2];
        #pragma unroll
        for (int m = 0; m < 4; m++)
            #pragma unroll
            for (int c = 0; c < 2; c++) wmma::fill_fragment(acc[m][c], 0.f);

        for (int j = 0; j < nIter; j++) {
            if (j < nIter - 1) cp_wait1();          // chunk j done (j+1 may remain)
            else               cp_wait0();
            wg_bar(g);                              // chunk j visible to WG;
                                                    // compute j-1 done -> stage (j+2)%3 free
            if (j + 2 < nIter) {
                int ci = 4 * (j + 2) + g, st = (j + 2) % N_STAGES;
                loadW(s0, s1, ci, st);
                loadA(s0, s1, ci, st);
                cp_commit();
            }
            const __half* As = Astage(j % N_STAGES);
            const __half* Ws = Wstage(j % N_STAGES) + (wc * 32) * ROWLEN;
            #pragma unroll
            for (int kk = 0; kk < 2; kk++) {
                wmma::fragment<wmma::matrix_b, 16, 16, 16, __half, wmma::col_major> bfr[2];
                wmma::load_matrix_sync(bfr[0], Ws + kk * 16, ROWLEN);
                wmma::load_matrix_sync(bfr[1], Ws + 16 * ROWLEN + kk * 16, ROWLEN);
                #pragma unroll
                for (int m = 0; m < 4; m++) {
                    wmma::fragment<wmma::matrix_a, 16, 16, 16, __half, wmma::row_major> afr;
                    wmma::load_matrix_sync(afr, As + (m * 16) * ROWLEN + kk * 16, ROWLEN);
                    wmma::mma_sync(acc[m][0], afr, bfr[0], acc[m][0]);
                    wmma::mma_sync(acc[m][1], afr, bfr[1], acc[m][1]);
                }
            }
        }

        __syncthreads();        // all WGs done computing; whole dsm reusable as Gs

        // 4 partial Gs regions at dsm base (4 x 34816 = 139264 <= 184320)
        float (*Gs)[136] = (float(*)[136])(dsm + (size_t)g * GS_BYTES);
        #pragma unroll
        for (int m = 0; m < 4; m++)
            #pragma unroll
            for (int c = 0; c < 2; c++)
                wmma::store_matrix_sync(&Gs[m * 16][wc * 32 + c * 16], acc[m][c],
                                        136, wmma::mem_row_major);
        __syncthreads();

        // ---- fused LSTM elementwise (sums the 4 WG partials, MUFU.TANH) ----
        {
            float (*G0)[136] = (float(*)[136])(dsm);
            float (*G1)[136] = (float(*)[136])(dsm + 1 * GS_BYTES);
            float (*G2)[136] = (float(*)[136])(dsm + 2 * GS_BYTES);
            float (*G3)[136] = (float(*)[136])(dsm + 3 * GS_BYTES);
            int pin = t & 1;
            int flag = ((t % 10) < 5) ? 1 : 0;
            const float* bias = (cell == 0) ? (flag ? g_b1f1 : g_b1f0)
                               : (cell == 1 ? g_b2 : g_b3);
            __half* hout = &g_h[pin ^ 1][cell][0][0];
            float*  cst  = &g_c[cell][0][0];
            #pragma unroll
            for (int it = 0; it < 4; it++) {
                int idx = it * 512 + tid;           // 64 x 32 = 2048
                int b = idx >> 5, jh = idx & 31;
                int hcol = h_base + jh;
                float gi = G0[b][jh]      + G1[b][jh]      + G2[b][jh]      + G3[b][jh]      + bias[hcol];
                float gf = G0[b][32 + jh] + G1[b][32 + jh] + G2[b][32 + jh] + G3[b][32 + jh] + bias[HID + hcol];
                float gg = G0[b][64 + jh] + G1[b][64 + jh] + G2[b][64 + jh] + G3[b][64 + jh] + bias[2 * HID + hcol];
                float go = G0[b][96 + jh] + G1[b][96 + jh] + G2[b][96 + jh] + G3[b][96 + jh] + bias[3 * HID + hcol];
                float si = fast_sigmoid(gi);
                float sf = fast_sigmoid(gf);
                float so = fast_sigmoid(go);
                float tg = fast_tanh(gg);
                float cold = cst[b * HID + hcol];
                float cn = fmaf(sf, cold, si * tg);
                float hn = so * fast_tanh(cn);
                cst[b * HID + hcol] = cn;
                __half hh = __float2half_rn(hn);
                hout[b * HID + hcol] = hh;
                if (cell == 2)
                    g_h2hist[(size_t)t * BATCH * HID + (size_t)b * HID + hcol] = hh;
            }
            __threadfence();                        // publish h before barrier
        }

        grid_barrier();

        // next step's first two chunks (need fresh h; Gs already consumed)
        if (t + 1 < T_LEN) {
            Seg n0, n1; segs(t + 1, n0, n1);
            loadW(n0, n1, g, 0); loadA(n0, n1, g, 0); cp_commit();
            loadW(n0, n1, 4 + g, 1); loadA(n0, n1, 4 + g, 1); cp_commit();
        }
    }
}

// ---------------- final batched output GEMM: out = h2hist @ Wd^T + bd ----------------
__global__ void __launch_bounds__(128) k_out(const float* __restrict__ bd,
                                             float* __restrict__ out) {
    __shared__ __align__(16) unsigned char sraw[32256];
    __half (*As)[64][72] = reinterpret_cast<__half(*)[64][72]>(sraw);
    __half (*Ws)[48][72] = reinterpret_cast<__half(*)[48][72]>(sraw + 18432);
    float (*Gs)[52]      = reinterpret_cast<float(*)[52]>(sraw);

    int tid = threadIdx.x, warp = tid >> 5;
    int r0 = blockIdx.x * 64;
    int f0 = blockIdx.y * 48;

    const __half* A = g_h2hist + (size_t)r0 * HID;

    wmma::fragment<wmma::accumulator, 16, 16, 16, float> acc[3];
    #pragma unroll
    for (int c = 0; c < 3; c++) wmma::fill_fragment(acc[c], 0.f);

    auto load_chunk = [&](int i, int s) {
        int k0 = i * 64;
        #pragma unroll
        for (int p = 0; p < 4; p++) {
            int idx = p * 128 + tid;
            int r = idx >> 3, c8 = idx & 7;
            cp16(&As[s][r][c8 * 8], A + (size_t)r * HID + k0 + c8 * 8);
        }
        #pragma unroll
        for (int p = 0; p < 3; p++) {
            int idx = p * 128 + tid;
            int r = idx >> 3, c8 = idx & 7;
            cp16(&Ws[s][r][c8 * 8], g_Wdp + (size_t)(f0 + r) * HID + k0 + c8 * 8);
        }
        cp_commit();
    };

    const int nch = HID / 64;
    load_chunk(0, 0);
    for (int i = 0; i < nch; i++) {
        if (i + 1 < nch) { load_chunk(i + 1, (i + 1) & 1); cp_wait1(); }
        else             { cp_wait0(); }
        __syncthreads();
        int s = i & 1;
        #pragma unroll
        for (int kk = 0; kk < 4; kk++) {
            wmma::fragment<wmma::matrix_a, 16, 16, 16, __half, wmma::row_major> afr;
            wmma::load_matrix_sync(afr, &As[s][warp * 16][kk * 16], 72);
            #pragma unroll
            for (int c = 0; c < 3; c++) {
                wmma::fragment<wmma::matrix_b, 16, 16, 16, __half, wmma::col_major> bfr;
                wmma::load_matrix_sync(bfr, &Ws[s][c * 16][kk * 16], 72);
                wmma::mma_sync(acc[c], afr, bfr, acc[c]);
            }
        }
        __syncthreads();
    }

    #pragma unroll
    for (int c = 0; c < 3; c++)
        wmma::store_matrix_sync(&Gs[warp * 16][c * 16], acc[c], 52, wmma::mem_row_major);
    __syncthreads();

    for (int idx = tid; idx < 64 * 48; idx += 128) {
        int rr = idx / 48, cc = idx % 48;
        int f = f0 + cc;
        if (f >= F_IN) continue;
        int r = r0 + rr;
        int tt = r >> 6, b = r & 63;
        out[(size_t)b * (T_LEN * F_IN) + (size_t)tt * F_IN + f] = Gs[rr][cc] + bd[f];
    }
}

// ---------------- launch ----------------
extern "C" void kernel_launch(void* const* d_in, const int* in_sizes, int n_in,
                              void* d_out, int out_size) {
    (void)in_sizes; (void)n_in; (void)out_size;
    const float* real_seq = (const float*)d_in[0];
    const float* Wih1 = (const float*)d_in[1];
    const float* Whh1 = (const float*)d_in[2];
    const float* bih1 = (const float*)d_in[3];
    const float* bhh1 = (const float*)d_in[4];
    const float* Wih2 = (const float*)d_in[5];
    const float* Whh2 = (const float*)d_in[6];
    const float* bih2 = (const float*)d_in[7];
    const float* bhh2 = (const float*)d_in[8];
    const float* Wih3 = (const float*)d_in[9];
    const float* Whh3 = (const float*)d_in[10];
    const float* bih3 = (const float*)d_in[11];
    const float* bhh3 = (const float*)d_in[12];
    const float* Wd   = (const float*)d_in[13];
    const float* bd   = (const float*)d_in[14];
    float* out = (float*)d_out;

    cudaFuncSetAttribute(k_persist, cudaFuncAttributeMaxDynamicSharedMemorySize, SMEM_P);

    // launches 1-3: setup; launch 4 = k_persist (ncu capture slot)
    k_setup<<<8192, 256>>>(Whh1, Wih2, Whh2, Wih3, Whh3, Wih1, Wd, real_seq);
    k_w1d<<<dim3(16, 64), 256>>>(Wih1, Wd);
    k_bias<<<16, 256>>>(bih1, bhh1, bih2, bhh2, bih3, bhh3, Wih1, bd);

    // launch 4: the whole 512-step recurrence
    k_persist<<<N_BLOCKS, 512, SMEM_P>>>();

    // batched output projection
    dim3 og((T_LEN * BATCH) / 64, 3);
    k_out<<<og, 128>>>(bd, out);
}

// round 15
// speedup vs baseline: 1.0394x; 1.0394x over previous
#include <cuda_runtime.h>
#include <cuda_fp16.h>
#include <mma.h>
#include <cstdint>

using namespace nvcuda;

#define BATCH 64
#define T_LEN 512
#define F_IN  132
#define F_PAD 192
#define HID   1024
#define G4    4096

#define N_BLOCKS 96

// ---------------- device global scratch ----------------
__device__ __half g_W5[5ULL * G4 * HID];              // Whh1, Wih2, Whh2, Wih3, Whh3
__device__ __half g_Wih1p[G4 * F_PAD];                // Wih1 padded 132->192
__device__ __half g_W1d[(size_t)G4 * HID];            // Wih1 @ Wd  (teacher-forcing fold)
__device__ __half g_Wdp[144 * HID];                   // Wd padded 132->144 rows
__device__ __half g_frames[(size_t)T_LEN * BATCH * F_PAD];
__device__ __half g_h2hist[(size_t)T_LEN * BATCH * HID];
__device__ __half g_h[2][3][BATCH][HID];              // ping-pong hidden states
__device__ float  g_c[3][BATCH][HID];                 // cell states fp32
__device__ float  g_b1f1[G4], g_b1f0[G4], g_b2[G4], g_b3[G4];

// grid barrier state (zero-initialized; sense-reversing, safe across replays)
__device__ unsigned g_gb_count;
__device__ unsigned g_gb_phase;

// ---------------- helpers ----------------
__device__ __forceinline__ void cp16(void* s, const void* g) {
    unsigned sa = (unsigned)__cvta_generic_to_shared(s);
    asm volatile("cp.async.cg.shared.global [%0], [%1], 16;\n" :: "r"(sa), "l"(g));
}
__device__ __forceinline__ void cp_commit() { asm volatile("cp.async.commit_group;\n"); }
__device__ __forceinline__ void cp_wait0()  { asm volatile("cp.async.wait_group 0;\n"); }
__device__ __forceinline__ void cp_wait1()  { asm volatile("cp.async.wait_group 1;\n"); }
__device__ __forceinline__ void wg_bar(int g) {
    asm volatile("bar.sync %0, 128;\n" :: "r"(1 + g) : "memory");
}
// hardware tanh (MUFU.TANH); sigmoid via exact identity 0.5*tanh(x/2)+0.5
__device__ __forceinline__ float fast_tanh(float x) {
    float y;
    asm("tanh.approx.f32 %0, %1;" : "=f"(y) : "f"(x));
    return y;
}
__device__ __forceinline__ float fast_sigmoid(float x) {
    return fmaf(0.5f, fast_tanh(0.5f * x), 0.5f);
}

// ---------------- fused setup kernel #1 ----------------
__global__ void k_setup(const float* __restrict__ Whh1, const float* __restrict__ Wih2,
                        const float* __restrict__ Whh2, const float* __restrict__ Wih3,
                        const float* __restrict__ Whh3, const float* __restrict__ Wih1,
                        const float* __restrict__ Wd,   const float* __restrict__ rs) {
    const size_t M  = (size_t)G4 * HID;
    const size_t N0 = 5 * M;
    const size_t N1 = (size_t)G4 * F_PAD;
    const size_t N2 = (size_t)144 * HID;
    const size_t N3 = (size_t)T_LEN * BATCH * F_PAD;
    const size_t N4 = 2ULL * 3 * BATCH * HID;
    const size_t N5 = 3ULL * BATCH * HID;
    const size_t T0 = N0, T1 = T0 + N1, T2 = T1 + N2, T3 = T2 + N3, T4 = T3 + N4,
                 T5 = T4 + N5;
    for (size_t i = (size_t)blockIdx.x * blockDim.x + threadIdx.x; i < T5;
         i += (size_t)gridDim.x * blockDim.x) {
        if (i < T0) {
            size_t m = i / M, r = i % M;
            const float* src = (m == 0) ? Whh1 : (m == 1) ? Wih2 : (m == 2) ? Whh2
                              : (m == 3) ? Wih3 : Whh3;
            g_W5[i] = __float2half_rn(src[r]);
        } else if (i < T1) {
            size_t j = i - T0;
            int c = (int)(j % F_PAD), r = (int)(j / F_PAD);
            g_Wih1p[j] = __float2half_rn(c < F_IN ? Wih1[(size_t)r * F_IN + c] : 0.f);
        } else if (i < T2) {
            size_t j = i - T1;
            int k = (int)(j % HID), r = (int)(j / HID);
            g_Wdp[j] = __float2half_rn(r < F_IN ? Wd[(size_t)r * HID + k] : 0.f);
        } else if (i < T3) {
            size_t j = i - T2;
            int c = (int)(j % F_PAD);
            size_t rem = j / F_PAD;
            int b = (int)(rem % BATCH), t = (int)(rem / BATCH);
            g_frames[j] = __float2half_rn(
                c < F_IN ? rs[((size_t)b * T_LEN + t) * F_IN + c] : 0.f);
        } else if (i < T4) {
            (&g_h[0][0][0][0])[i - T3] = __float2half_rn(0.f);
        } else {
            (&g_c[0][0][0])[i - T4] = 0.f;
        }
    }
}

// ---------------- setup kernel #2: W1d = Wih1 @ Wd ----------------
__global__ void __launch_bounds__(256) k_w1d(const float* __restrict__ Wih1,
                                             const float* __restrict__ Wd) {
    __shared__ float ws[64][133];
    int jb = blockIdx.y * 64, kb = blockIdx.x * 64;
    for (int idx = threadIdx.x; idx < 64 * F_IN; idx += 256) {
        int r = idx / F_IN, c = idx % F_IN;
        ws[r][c] = Wih1[(size_t)(jb + r) * F_IN + c];
    }
    __syncthreads();
    int tx = threadIdx.x & 15, ty = threadIdx.x >> 4;
    float acc[4][4] = {};
    const float* wdp = Wd + kb + tx * 4;
    for (int f = 0; f < F_IN; f++) {
        float4 d = *(const float4*)(wdp + (size_t)f * HID);
        float a0 = ws[ty * 4 + 0][f], a1 = ws[ty * 4 + 1][f];
        float a2 = ws[ty * 4 + 2][f], a3 = ws[ty * 4 + 3][f];
        acc[0][0] += a0 * d.x; acc[0][1] += a0 * d.y; acc[0][2] += a0 * d.z; acc[0][3] += a0 * d.w;
        acc[1][0] += a1 * d.x; acc[1][1] += a1 * d.y; acc[1][2] += a1 * d.z; acc[1][3] += a1 * d.w;
        acc[2][0] += a2 * d.x; acc[2][1] += a2 * d.y; acc[2][2] += a2 * d.z; acc[2][3] += a2 * d.w;
        acc[3][0] += a3 * d.x; acc[3][1] += a3 * d.y; acc[3][2] += a3 * d.z; acc[3][3] += a3 * d.w;
    }
    #pragma unroll
    for (int jj = 0; jj < 4; jj++) {
        int j = jb + ty * 4 + jj;
        #pragma unroll
        for (int kk = 0; kk < 4; kk++)
            g_W1d[(size_t)j * HID + kb + tx * 4 + kk] = __float2half_rn(acc[jj][kk]);
    }
}

// ---------------- setup kernel #3: biases ----------------
__global__ void k_bias(const float* __restrict__ bih1, const float* __restrict__ bhh1,
                       const float* __restrict__ bih2, const float* __restrict__ bhh2,
                       const float* __restrict__ bih3, const float* __restrict__ bhh3,
                       const float* __restrict__ Wih1, const float* __restrict__ bd) {
    int j = blockIdx.x * blockDim.x + threadIdx.x;
    if (j >= G4) return;
    float b1 = bih1[j] + bhh1[j];
    float acc = 0.f;
    for (int f = 0; f < F_IN; f++) acc += Wih1[(size_t)j * F_IN + f] * bd[f];
    g_b1f1[j] = b1;
    g_b1f0[j] = b1 + acc;
    g_b2[j] = bih2[j] + bhh2[j];
    g_b3[j] = bih3[j] + bhh3[j];
}

// ---------------- persistent recurrence kernel ----------------
// R12 champion structure + ONE change: next-step W prefetch issued inside the
// split-open grid barrier (after elementwise consumed Gs, before arrival
// atomics) so the barrier convergence hides the W fetch; in-loop j=0 skips
// its stage-1 W load on t>0.
struct Seg { const __half* a; int lda; const __half* w; int ldw; int nch; };

#define A_STG 9216                        // 64 x 72 halves
#define W_STG 18432                       // 128 x 72 halves
#define N_STAGES 2
#define W_REGION (4 * N_STAGES * W_STG)   // 147456
#define SMEM_P (W_REGION + 4 * N_STAGES * A_STG) // 221184
#define GS_BYTES 34816                    // 64 x 136 floats

__global__ void __launch_bounds__(512, 1) k_persist() {
    extern __shared__ __align__(16) unsigned char dsm[];

    const int tid  = threadIdx.x;
    const int warp = tid >> 5;
    const int g    = warp >> 2;          // warpgroup 0..3: K residue class
    const int wc   = warp & 3;           // gate-col quarter (32 cols)
    const int wtid = tid & 127;
    const int cell = blockIdx.x >> 5;
    const int h_base = (blockIdx.x & 31) << 5;   // 32 hidden cols

    const size_t M = (size_t)G4 * HID;

    auto Wstage = [&](int st) -> __half* {
        return (__half*)(dsm + (size_t)(g * N_STAGES + st) * W_STG);
    };
    auto Astage = [&](int st) -> __half* {
        return (__half*)(dsm + W_REGION + (size_t)(g * N_STAGES + st) * A_STG);
    };

    auto segs = [&](int t, Seg& s0, Seg& s1) {
        int pin = t & 1;
        int flag = ((t % 10) < 5) ? 1 : 0;
        const __half* hin = &g_h[pin][0][0][0];
        const __half* h0 = hin;
        const __half* h1 = hin + BATCH * HID;
        const __half* h2 = hin + 2 * BATCH * HID;
        if (cell == 0) {
            if (flag) s0 = { g_frames + (size_t)t * BATCH * F_PAD, F_PAD, g_Wih1p, F_PAD, F_PAD / 64 };
            else      s0 = { h2, HID, g_W1d, HID, HID / 64 };
            s1 = { h0, HID, g_W5, HID, HID / 64 };
        } else if (cell == 1) {
            s0 = { h0, HID, g_W5 + 1 * M, HID, HID / 64 };
            s1 = { h1, HID, g_W5 + 2 * M, HID, HID / 64 };
        } else {
            s0 = { h1, HID, g_W5 + 3 * M, HID, HID / 64 };
            s1 = { h2, HID, g_W5 + 4 * M, HID, HID / 64 };
        }
    };

    auto loadW = [&](const Seg& s0, const Seg& s1, int ci, int st) {
        const Seg& sg = (ci < s0.nch) ? s0 : s1;
        int k0 = ((ci < s0.nch) ? ci : ci - s0.nch) * 64;
        __half* W = Wstage(st);
        #pragma unroll
        for (int p = 0; p < 8; p++) {
            int idx = p * 128 + wtid;
            int r = idx >> 3, c8 = idx & 7;
            int grow = ((r >> 5) << 10) + h_base + (r & 31);
            cp16(W + r * 72 + c8 * 8, sg.w + (size_t)grow * sg.ldw + k0 + c8 * 8);
        }
    };
    auto loadA = [&](const Seg& s0, const Seg& s1, int ci, int st) {
        const Seg& sg = (ci < s0.nch) ? s0 : s1;
        int k0 = ((ci < s0.nch) ? ci : ci - s0.nch) * 64;
        __half* A = Astage(st);
        #pragma unroll
        for (int p = 0; p < 4; p++) {
            int idx = p * 128 + wtid;
            int r = idx >> 3, c8 = idx & 7;
            cp16(A + r * 72 + c8 * 8, sg.a + (size_t)r * sg.lda + k0 + c8 * 8);
        }
    };

    // t=0 prologue: each WG loads its first chunk (ci = g) into stage 0
    {
        Seg s0, s1; segs(0, s0, s1);
        loadW(s0, s1, g, 0);
        loadA(s0, s1, g, 0);
        cp_commit();
    }

    for (int t = 0; t < T_LEN; t++) {
        Seg s0, s1; segs(t, s0, s1);
        const int nch = s0.nch + s1.nch;            // 19 or 32
        const int nIter = (nch - g + 3) >> 2;       // this WG's chunk count
        const bool w_pre = (t > 0);                 // stage-0/1 W pre-loaded pre-barrier

        wmma::fragment<wmma::accumulator, 16, 16, 16, float> acc[4][2];
        #pragma unroll
        for (int m = 0; m < 4; m++)
            #pragma unroll
            for (int c = 0; c < 2; c++) wmma::fill_fragment(acc[m][c], 0.f);

        for (int j = 0; j < nIter; j++) {
            cp_wait0();                             // own chunk-j cps done
            wg_bar(g);                              // chunk j visible; other stage free
            if (j + 1 < nIter) {                    // prefetch next chunk
                int ci = 4 * (j + 1) + g, st = (j + 1) & 1;
                if (!(w_pre && j == 0)) loadW(s0, s1, ci, st);  // st1 W pre-loaded
                loadA(s0, s1, ci, st);
                cp_commit();
            }
            const __half* As = Astage(j & 1);
            const __half* Ws = Wstage(j & 1) + (wc * 32) * 72;
            #pragma unroll
            for (int kk = 0; kk < 4; kk++) {
                wmma::fragment<wmma::matrix_b, 16, 16, 16, __half, wmma::col_major> bfr[2];
                wmma::load_matrix_sync(bfr[0], Ws + kk * 16, 72);
                wmma::load_matrix_sync(bfr[1], Ws + 16 * 72 + kk * 16, 72);
                #pragma unroll
                for (int m = 0; m < 4; m++) {
                    wmma::fragment<wmma::matrix_a, 16, 16, 16, __half, wmma::row_major> afr;
                    wmma::load_matrix_sync(afr, As + (m * 16) * 72 + kk * 16, 72);
                    wmma::mma_sync(acc[m][0], afr, bfr[0], acc[m][0]);
                    wmma::mma_sync(acc[m][1], afr, bfr[1], acc[m][1]);
                }
            }
        }

        __syncthreads();        // all WGs done computing; stage region reusable as Gs

        // 4 partial Gs regions (overlay W-stage region; 139264 <= 147456)
        float (*Gs)[136] = (float(*)[136])(dsm + (size_t)g * GS_BYTES);
        #pragma unroll
        for (int m = 0; m < 4; m++)
            #pragma unroll
            for (int c = 0; c < 2; c++)
                wmma::store_matrix_sync(&Gs[m * 16][wc * 32 + c * 16], acc[m][c],
                                        136, wmma::mem_row_major);
        __syncthreads();

        // ---- fused LSTM elementwise (sums the 4 WG partials, MUFU.TANH) ----
        {
            float (*G0)[136] = (float(*)[136])(dsm);
            float (*G1)[136] = (float(*)[136])(dsm + 1 * GS_BYTES);
            float (*G2)[136] = (float(*)[136])(dsm + 2 * GS_BYTES);
            float (*G3)[136] = (float(*)[136])(dsm + 3 * GS_BYTES);
            int pin = t & 1;
            int flag = ((t % 10) < 5) ? 1 : 0;
            const float* bias = (cell == 0) ? (flag ? g_b1f1 : g_b1f0)
                               : (cell == 1 ? g_b2 : g_b3);
            __half* hout = &g_h[pin ^ 1][cell][0][0];
            float*  cst  = &g_c[cell][0][0];
            #pragma unroll
            for (int it = 0; it < 4; it++) {
                int idx = it * 512 + tid;           // 64 x 32 = 2048
                int b = idx >> 5, jh = idx & 31;
                int hcol = h_base + jh;
                float gi = G0[b][jh]      + G1[b][jh]      + G2[b][jh]      + G3[b][jh]      + bias[hcol];
                float gf = G0[b][32 + jh] + G1[b][32 + jh] + G2[b][32 + jh] + G3[b][32 + jh] + bias[HID + hcol];
                float gg = G0[b][64 + jh] + G1[b][64 + jh] + G2[b][64 + jh] + G3[b][64 + jh] + bias[2 * HID + hcol];
                float go = G0[b][96 + jh] + G1[b][96 + jh] + G2[b][96 + jh] + G3[b][96 + jh] + bias[3 * HID + hcol];
                float si = fast_sigmoid(gi);
                float sf = fast_sigmoid(gf);
                float so = fast_sigmoid(go);
                float tg = fast_tanh(gg);
                float cold = cst[b * HID + hcol];
                float cn = fmaf(sf, cold, si * tg);
                float hn = so * fast_tanh(cn);
                cst[b * HID + hcol] = cn;
                __half hh = __float2half_rn(hn);
                hout[b * HID + hcol] = hh;
                if (cell == 2)
                    g_h2hist[(size_t)t * BATCH * HID + (size_t)b * HID + hcol] = hh;
            }
            __threadfence();                        // publish h before barrier
        }

        // ---- split-open grid barrier with W prefetch hidden under it ----
        const bool more = (t + 1 < T_LEN);
        Seg n0, n1;
        if (more) segs(t + 1, n0, n1);

        __syncthreads();                            // Gs fully consumed; W stages free
        if (more) {                                 // issue next-step W (h-independent)
            loadW(n0, n1, g, 0);
            loadW(n0, n1, 4 + g, 1);                // uncommitted; grouped with A below
        }
        if (tid == 0) {
            unsigned snap = *(volatile unsigned*)&g_gb_phase;
            __threadfence();
            unsigned old = atomicAdd(&g_gb_count, 1);
            if (old == N_BLOCKS - 1) {
                atomicExch(&g_gb_count, 0);
                __threadfence();
                atomicAdd(&g_gb_phase, 1);
            } else {
                while (*(volatile unsigned*)&g_gb_phase == snap) __nanosleep(64);
            }
            __threadfence();
        }
        __syncthreads();

        if (more) {                                 // A needs fresh h (post-barrier)
            loadA(n0, n1, g, 0);
            cp_commit();                            // group = {W(g,0), W(4+g,1), A(g,0)}
        }
    }
}

// ---------------- final batched output GEMM: out = h2hist @ Wd^T + bd ----------------
__global__ void __launch_bounds__(128) k_out(const float* __restrict__ bd,
                                             float* __restrict__ out) {
    __shared__ __align__(16) unsigned char sraw[32256];
    __half (*As)[64][72] = reinterpret_cast<__half(*)[64][72]>(sraw);
    __half (*Ws)[48][72] = reinterpret_cast<__half(*)[48][72]>(sraw + 18432);
    float (*Gs)[52]      = reinterpret_cast<float(*)[52]>(sraw);

    int tid = threadIdx.x, warp = tid >> 5;
    int r0 = blockIdx.x * 64;
    int f0 = blockIdx.y * 48;

    const __half* A = g_h2hist + (size_t)r0 * HID;

    wmma::fragment<wmma::accumulator, 16, 16, 16, float> acc[3];
    #pragma unroll
    for (int c = 0; c < 3; c++) wmma::fill_fragment(acc[c], 0.f);

    auto load_chunk = [&](int i, int s) {
        int k0 = i * 64;
        #pragma unroll
        for (int p = 0; p < 4; p++) {
            int idx = p * 128 + tid;
            int r = idx >> 3, c8 = idx & 7;
            cp16(&As[s][r][c8 * 8], A + (size_t)r * HID + k0 + c8 * 8);
        }
        #pragma unroll
        for (int p = 0; p < 3; p++) {
            int idx = p * 128 + tid;
            int r = idx >> 3, c8 = idx & 7;
            cp16(&Ws[s][r][c8 * 8], g_Wdp + (size_t)(f0 + r) * HID + k0 + c8 * 8);
        }
        cp_commit();
    };

    const int nch = HID / 64;
    load_chunk(0, 0);
    for (int i = 0; i < nch; i++) {
        if (i + 1 < nch) { load_chunk(i + 1, (i + 1) & 1); cp_wait1(); }
        else             { cp_wait0(); }
        __syncthreads();
        int s = i & 1;
        #pragma unroll
        for (int kk = 0; kk < 4; kk++) {
            wmma::fragment<wmma::matrix_a, 16, 16, 16, __half, wmma::row_major> afr;
            wmma::load_matrix_sync(afr, &As[s][warp * 16][kk * 16], 72);
            #pragma unroll
            for (int c = 0; c < 3; c++) {
                wmma::fragment<wmma::matrix_b, 16, 16, 16, __half, wmma::col_major> bfr;
                wmma::load_matrix_sync(bfr, &Ws[s][c * 16][kk * 16], 72);
                wmma::mma_sync(acc[c], afr, bfr, acc[c]);
            }
        }
        __syncthreads();
    }

    #pragma unroll
    for (int c = 0; c < 3; c++)
        wmma::store_matrix_sync(&Gs[warp * 16][c * 16], acc[c], 52, wmma::mem_row_major);
    __syncthreads();

    for (int idx = tid; idx < 64 * 48; idx += 128) {
        int rr = idx / 48, cc = idx % 48;
        int f = f0 + cc;
        if (f >= F_IN) continue;
        int r = r0 + rr;
        int tt = r >> 6, b = r & 63;
        out[(size_t)b * (T_LEN * F_IN) + (size_t)tt * F_IN + f] = Gs[rr][cc] + bd[f];
    }
}

// ---------------- launch ----------------
extern "C" void kernel_launch(void* const* d_in, const int* in_sizes, int n_in,
                              void* d_out, int out_size) {
    (void)in_sizes; (void)n_in; (void)out_size;
    const float* real_seq = (const float*)d_in[0];
    const float* Wih1 = (const float*)d_in[1];
    const float* Whh1 = (const float*)d_in[2];
    const float* bih1 = (const float*)d_in[3];
    const float* bhh1 = (const float*)d_in[4];
    const float* Wih2 = (const float*)d_in[5];
    const float* Whh2 = (const float*)d_in[6];
    const float* bih2 = (const float*)d_in[7];
    const float* bhh2 = (const float*)d_in[8];
    const float* Wih3 = (const float*)d_in[9];
    const float* Whh3 = (const float*)d_in[10];
    const float* bih3 = (const float*)d_in[11];
    const float* bhh3 = (const float*)d_in[12];
    const float* Wd   = (const float*)d_in[13];
    const float* bd   = (const float*)d_in[14];
    float* out = (float*)d_out;

    cudaFuncSetAttribute(k_persist, cudaFuncAttributeMaxDynamicSharedMemorySize, SMEM_P);

    // launches 1-3: setup; launch 4 = k_persist (ncu capture slot)
    k_setup<<<8192, 256>>>(Whh1, Wih2, Whh2, Wih3, Whh3, Wih1, Wd, real_seq);
    k_w1d<<<dim3(16, 64), 256>>>(Wih1, Wd);
    k_bias<<<16, 256>>>(bih1, bhh1, bih2, bhh2, bih3, bhh3, Wih1, bd);

    // launch 4: the whole 512-step recurrence
    k_persist<<<N_BLOCKS, 512, SMEM_P>>>();

    // batched output projection
    dim3 og((T_LEN * BATCH) / 64, 3);
    k_out<<<og, 128>>>(bd, out);
}

// round 16
// speedup vs baseline: 1.1150x; 1.0728x over previous
#include <cuda_runtime.h>
#include <cuda_fp16.h>
#include <mma.h>
#include <cstdint>

using namespace nvcuda;

#define BATCH 64
#define T_LEN 512
#define F_IN  132
#define F_PAD 192
#define HID   1024
#define G4    4096

#define N_BLOCKS 96

// ---------------- device global scratch ----------------
__device__ __half g_W5[5ULL * G4 * HID];              // Whh1, Wih2, Whh2, Wih3, Whh3
__device__ __half g_Wih1p[G4 * F_PAD];                // Wih1 padded 132->192
__device__ __half g_W1d[(size_t)G4 * HID];            // Wih1 @ Wd  (teacher-forcing fold)
__device__ __half g_Wdp[144 * HID];                   // Wd padded 132->144 rows
__device__ __half g_frames[(size_t)T_LEN * BATCH * F_PAD];
__device__ __half g_h2hist[(size_t)T_LEN * BATCH * HID];
__device__ __half g_h[2][3][BATCH][HID];              // ping-pong hidden states
__device__ float  g_c[3][BATCH][HID];                 // cell states fp32
__device__ float  g_b1f1[G4], g_b1f0[G4], g_b2[G4], g_b3[G4];

// grid barrier state (zero-initialized; sense-reversing, safe across replays)
__device__ unsigned g_gb_count;
__device__ unsigned g_gb_phase;

// ---------------- helpers ----------------
__device__ __forceinline__ void cp16(void* s, const void* g) {
    unsigned sa = (unsigned)__cvta_generic_to_shared(s);
    asm volatile("cp.async.cg.shared.global [%0], [%1], 16;\n" :: "r"(sa), "l"(g));
}
__device__ __forceinline__ void cp_commit() { asm volatile("cp.async.commit_group;\n"); }
__device__ __forceinline__ void cp_wait0()  { asm volatile("cp.async.wait_group 0;\n"); }
__device__ __forceinline__ void cp_wait1()  { asm volatile("cp.async.wait_group 1;\n"); }
__device__ __forceinline__ void wg_bar(int g) {
    asm volatile("bar.sync %0, 128;\n" :: "r"(1 + g) : "memory");
}
// hardware tanh (MUFU.TANH); sigmoid via exact identity 0.5*tanh(x/2)+0.5
__device__ __forceinline__ float fast_tanh(float x) {
    float y;
    asm("tanh.approx.f32 %0, %1;" : "=f"(y) : "f"(x));
    return y;
}
__device__ __forceinline__ float fast_sigmoid(float x) {
    return fmaf(0.5f, fast_tanh(0.5f * x), 0.5f);
}

// ---------------- fused setup kernel #1 ----------------
__global__ void k_setup(const float* __restrict__ Whh1, const float* __restrict__ Wih2,
                        const float* __restrict__ Whh2, const float* __restrict__ Wih3,
                        const float* __restrict__ Whh3, const float* __restrict__ Wih1,
                        const float* __restrict__ Wd,   const float* __restrict__ rs) {
    const size_t M  = (size_t)G4 * HID;
    const size_t N0 = 5 * M;
    const size_t N1 = (size_t)G4 * F_PAD;
    const size_t N2 = (size_t)144 * HID;
    const size_t N3 = (size_t)T_LEN * BATCH * F_PAD;
    const size_t N4 = 2ULL * 3 * BATCH * HID;
    const size_t N5 = 3ULL * BATCH * HID;
    const size_t T0 = N0, T1 = T0 + N1, T2 = T1 + N2, T3 = T2 + N3, T4 = T3 + N4,
                 T5 = T4 + N5;
    for (size_t i = (size_t)blockIdx.x * blockDim.x + threadIdx.x; i < T5;
         i += (size_t)gridDim.x * blockDim.x) {
        if (i < T0) {
            size_t m = i / M, r = i % M;
            const float* src = (m == 0) ? Whh1 : (m == 1) ? Wih2 : (m == 2) ? Whh2
                              : (m == 3) ? Wih3 : Whh3;
            g_W5[i] = __float2half_rn(src[r]);
        } else if (i < T1) {
            size_t j = i - T0;
            int c = (int)(j % F_PAD), r = (int)(j / F_PAD);
            g_Wih1p[j] = __float2half_rn(c < F_IN ? Wih1[(size_t)r * F_IN + c] : 0.f);
        } else if (i < T2) {
            size_t j = i - T1;
            int k = (int)(j % HID), r = (int)(j / HID);
            g_Wdp[j] = __float2half_rn(r < F_IN ? Wd[(size_t)r * HID + k] : 0.f);
        } else if (i < T3) {
            size_t j = i - T2;
            int c = (int)(j % F_PAD);
            size_t rem = j / F_PAD;
            int b = (int)(rem % BATCH), t = (int)(rem / BATCH);
            g_frames[j] = __float2half_rn(
                c < F_IN ? rs[((size_t)b * T_LEN + t) * F_IN + c] : 0.f);
        } else if (i < T4) {
            (&g_h[0][0][0][0])[i - T3] = __float2half_rn(0.f);
        } else {
            (&g_c[0][0][0])[i - T4] = 0.f;
        }
    }
}

// ---------------- setup kernel #2: W1d = Wih1 @ Wd ----------------
__global__ void __launch_bounds__(256) k_w1d(const float* __restrict__ Wih1,
                                             const float* __restrict__ Wd) {
    __shared__ float ws[64][133];
    int jb = blockIdx.y * 64, kb = blockIdx.x * 64;
    for (int idx = threadIdx.x; idx < 64 * F_IN; idx += 256) {
        int r = idx / F_IN, c = idx % F_IN;
        ws[r][c] = Wih1[(size_t)(jb + r) * F_IN + c];
    }
    __syncthreads();
    int tx = threadIdx.x & 15, ty = threadIdx.x >> 4;
    float acc[4][4] = {};
    const float* wdp = Wd + kb + tx * 4;
    for (int f = 0; f < F_IN; f++) {
        float4 d = *(const float4*)(wdp + (size_t)f * HID);
        float a0 = ws[ty * 4 + 0][f], a1 = ws[ty * 4 + 1][f];
        float a2 = ws[ty * 4 + 2][f], a3 = ws[ty * 4 + 3][f];
        acc[0][0] += a0 * d.x; acc[0][1] += a0 * d.y; acc[0][2] += a0 * d.z; acc[0][3] += a0 * d.w;
        acc[1][0] += a1 * d.x; acc[1][1] += a1 * d.y; acc[1][2] += a1 * d.z; acc[1][3] += a1 * d.w;
        acc[2][0] += a2 * d.x; acc[2][1] += a2 * d.y; acc[2][2] += a2 * d.z; acc[2][3] += a2 * d.w;
        acc[3][0] += a3 * d.x; acc[3][1] += a3 * d.y; acc[3][2] += a3 * d.z; acc[3][3] += a3 * d.w;
    }
    #pragma unroll
    for (int jj = 0; jj < 4; jj++) {
        int j = jb + ty * 4 + jj;
        #pragma unroll
        for (int kk = 0; kk < 4; kk++)
            g_W1d[(size_t)j * HID + kb + tx * 4 + kk] = __float2half_rn(acc[jj][kk]);
    }
}

// ---------------- setup kernel #3: biases ----------------
__global__ void k_bias(const float* __restrict__ bih1, const float* __restrict__ bhh1,
                       const float* __restrict__ bih2, const float* __restrict__ bhh2,
                       const float* __restrict__ bih3, const float* __restrict__ bhh3,
                       const float* __restrict__ Wih1, const float* __restrict__ bd) {
    int j = blockIdx.x * blockDim.x + threadIdx.x;
    if (j >= G4) return;
    float b1 = bih1[j] + bhh1[j];
    float acc = 0.f;
    for (int f = 0; f < F_IN; f++) acc += Wih1[(size_t)j * F_IN + f] * bd[f];
    g_b1f1[j] = b1;
    g_b1f0[j] = b1 + acc;
    g_b2[j] = bih2[j] + bhh2[j];
    g_b3[j] = bih3[j] + bhh3[j];
}

// ---------------- persistent recurrence kernel ----------------
// R12 champion + three local epilogue opts: no per-thread threadfence
// (grid barrier's tid0 fence is the release), c-state float4 register
// prefetch, fully vectorized elementwise (float4 Gs/bias/c, 8B h stores).
struct Seg { const __half* a; int lda; const __half* w; int ldw; int nch; };

#define A_STG 9216                        // 64 x 72 halves
#define W_STG 18432                       // 128 x 72 halves
#define N_STAGES 2
#define W_REGION (4 * N_STAGES * W_STG)   // 147456
#define SMEM_P (W_REGION + 4 * N_STAGES * A_STG) // 221184
#define GS_BYTES 34816                    // 64 x 136 floats

__device__ __forceinline__ void grid_barrier() {
    __syncthreads();
    if (threadIdx.x == 0) {
        unsigned snap = *(volatile unsigned*)&g_gb_phase;
        __threadfence();
        unsigned old = atomicAdd(&g_gb_count, 1);
        if (old == N_BLOCKS - 1) {
            atomicExch(&g_gb_count, 0);
            __threadfence();
            atomicAdd(&g_gb_phase, 1);
        } else {
            while (*(volatile unsigned*)&g_gb_phase == snap) __nanosleep(64);
        }
        __threadfence();
    }
    __syncthreads();
}

__global__ void __launch_bounds__(512, 1) k_persist() {
    extern __shared__ __align__(16) unsigned char dsm[];

    const int tid  = threadIdx.x;
    const int warp = tid >> 5;
    const int g    = warp >> 2;          // warpgroup 0..3: K residue class
    const int wc   = warp & 3;           // gate-col quarter (32 cols)
    const int wtid = tid & 127;
    const int cell = blockIdx.x >> 5;
    const int h_base = (blockIdx.x & 31) << 5;   // 32 hidden cols

    // epilogue coordinates: thread = (batch eb, 4 consecutive hid cols)
    const int eq = tid & 7;              // col group (4 cols)
    const int eb = tid >> 3;             // batch row 0..63
    const int ejh = eq * 4;              // first of 4 cols
    const int ehcol = h_base + ejh;

    const size_t M = (size_t)G4 * HID;

    auto Wstage = [&](int st) -> __half* {
        return (__half*)(dsm + (size_t)(g * N_STAGES + st) * W_STG);
    };
    auto Astage = [&](int st) -> __half* {
        return (__half*)(dsm + W_REGION + (size_t)(g * N_STAGES + st) * A_STG);
    };

    auto segs = [&](int t, Seg& s0, Seg& s1) {
        int pin = t & 1;
        int flag = ((t % 10) < 5) ? 1 : 0;
        const __half* hin = &g_h[pin][0][0][0];
        const __half* h0 = hin;
        const __half* h1 = hin + BATCH * HID;
        const __half* h2 = hin + 2 * BATCH * HID;
        if (cell == 0) {
            if (flag) s0 = { g_frames + (size_t)t * BATCH * F_PAD, F_PAD, g_Wih1p, F_PAD, F_PAD / 64 };
            else      s0 = { h2, HID, g_W1d, HID, HID / 64 };
            s1 = { h0, HID, g_W5, HID, HID / 64 };
        } else if (cell == 1) {
            s0 = { h0, HID, g_W5 + 1 * M, HID, HID / 64 };
            s1 = { h1, HID, g_W5 + 2 * M, HID, HID / 64 };
        } else {
            s0 = { h1, HID, g_W5 + 3 * M, HID, HID / 64 };
            s1 = { h2, HID, g_W5 + 4 * M, HID, HID / 64 };
        }
    };

    auto loadW = [&](const Seg& s0, const Seg& s1, int ci, int st) {
        const Seg& sg = (ci < s0.nch) ? s0 : s1;
        int k0 = ((ci < s0.nch) ? ci : ci - s0.nch) * 64;
        __half* W = Wstage(st);
        #pragma unroll
        for (int p = 0; p < 8; p++) {
            int idx = p * 128 + wtid;
            int r = idx >> 3, c8 = idx & 7;
            int grow = ((r >> 5) << 10) + h_base + (r & 31);
            cp16(W + r * 72 + c8 * 8, sg.w + (size_t)grow * sg.ldw + k0 + c8 * 8);
        }
    };
    auto loadA = [&](const Seg& s0, const Seg& s1, int ci, int st) {
        const Seg& sg = (ci < s0.nch) ? s0 : s1;
        int k0 = ((ci < s0.nch) ? ci : ci - s0.nch) * 64;
        __half* A = Astage(st);
        #pragma unroll
        for (int p = 0; p < 4; p++) {
            int idx = p * 128 + wtid;
            int r = idx >> 3, c8 = idx & 7;
            cp16(A + r * 72 + c8 * 8, sg.a + (size_t)r * sg.lda + k0 + c8 * 8);
        }
    };

    float* cst = &g_c[cell][0][0];

    // t=0 prologue: each WG loads its first chunk (ci = g) into stage 0
    {
        Seg s0, s1; segs(0, s0, s1);
        loadW(s0, s1, g, 0);
        loadA(s0, s1, g, 0);
        cp_commit();
    }

    for (int t = 0; t < T_LEN; t++) {
        Seg s0, s1; segs(t, s0, s1);
        const int nch = s0.nch + s1.nch;            // 19 or 32
        const int nIter = (nch - g + 3) >> 2;       // this WG's chunk count

        wmma::fragment<wmma::accumulator, 16, 16, 16, float> acc[4][2];
        #pragma unroll
        for (int m = 0; m < 4; m++)
            #pragma unroll
            for (int c = 0; c < 2; c++) wmma::fill_fragment(acc[m][c], 0.f);

        for (int j = 0; j < nIter; j++) {
            cp_wait0();                             // own chunk-j cps done
            wg_bar(g);                              // chunk j visible; other stage free
            if (j + 1 < nIter) {                    // prefetch next chunk
                int ci = 4 * (j + 1) + g, st = (j + 1) & 1;
                loadW(s0, s1, ci, st);
                loadA(s0, s1, ci, st);
                cp_commit();
            }
            const __half* As = Astage(j & 1);
            const __half* Ws = Wstage(j & 1) + (wc * 32) * 72;
            #pragma unroll
            for (int kk = 0; kk < 4; kk++) {
                wmma::fragment<wmma::matrix_b, 16, 16, 16, __half, wmma::col_major> bfr[2];
                wmma::load_matrix_sync(bfr[0], Ws + kk * 16, 72);
                wmma::load_matrix_sync(bfr[1], Ws + 16 * 72 + kk * 16, 72);
                #pragma unroll
                for (int m = 0; m < 4; m++) {
                    wmma::fragment<wmma::matrix_a, 16, 16, 16, __half, wmma::row_major> afr;
                    wmma::load_matrix_sync(afr, As + (m * 16) * 72 + kk * 16, 72);
                    wmma::mma_sync(acc[m][0], afr, bfr[0], acc[m][0]);
                    wmma::mma_sync(acc[m][1], afr, bfr[1], acc[m][1]);
                }
            }
        }

        // c-state register prefetch (hides L2 latency under the sync/stores)
        float4 cv = *(const float4*)(cst + eb * HID + ehcol);

        __syncthreads();        // all WGs done computing; stage region reusable as Gs

        // 4 partial Gs regions (overlay W-stage region; 139264 <= 147456)
        float (*Gs)[136] = (float(*)[136])(dsm + (size_t)g * GS_BYTES);
        #pragma unroll
        for (int m = 0; m < 4; m++)
            #pragma unroll
            for (int c = 0; c < 2; c++)
                wmma::store_matrix_sync(&Gs[m * 16][wc * 32 + c * 16], acc[m][c],
                                        136, wmma::mem_row_major);
        __syncthreads();

        // ---- fused LSTM elementwise: vectorized (float4 / 8B) ----
        {
            float (*G0)[136] = (float(*)[136])(dsm);
            float (*G1)[136] = (float(*)[136])(dsm + 1 * GS_BYTES);
            float (*G2)[136] = (float(*)[136])(dsm + 2 * GS_BYTES);
            float (*G3)[136] = (float(*)[136])(dsm + 3 * GS_BYTES);
            int pin = t & 1;
            int flag = ((t % 10) < 5) ? 1 : 0;
            const float* bias = (cell == 0) ? (flag ? g_b1f1 : g_b1f0)
                               : (cell == 1 ? g_b2 : g_b3);
            __half* hout = &g_h[pin ^ 1][cell][0][0];

            auto sum4 = [&](int off) -> float4 {
                float4 a = *(const float4*)&G0[eb][off];
                float4 b4 = *(const float4*)&G1[eb][off];
                float4 c4 = *(const float4*)&G2[eb][off];
                float4 d4 = *(const float4*)&G3[eb][off];
                float4 bi = *(const float4*)&bias[(off >> 5) * HID + ehcol];
                return make_float4(a.x + b4.x + c4.x + d4.x + bi.x,
                                   a.y + b4.y + c4.y + d4.y + bi.y,
                                   a.z + b4.z + c4.z + d4.z + bi.z,
                                   a.w + b4.w + c4.w + d4.w + bi.w);
            };
            float4 gi = sum4(ejh);
            float4 gf = sum4(32 + ejh);
            float4 gg = sum4(64 + ejh);
            float4 go = sum4(96 + ejh);

            float cn[4], hn[4];
            const float* gip = &gi.x; const float* gfp = &gf.x;
            const float* ggp = &gg.x; const float* gop = &go.x;
            const float* cvp = &cv.x;
            #pragma unroll
            for (int x = 0; x < 4; x++) {
                float si = fast_sigmoid(gip[x]);
                float sf = fast_sigmoid(gfp[x]);
                float so = fast_sigmoid(gop[x]);
                float tg = fast_tanh(ggp[x]);
                cn[x] = fmaf(sf, cvp[x], si * tg);
                hn[x] = so * fast_tanh(cn[x]);
            }
            *(float4*)(cst + eb * HID + ehcol) = make_float4(cn[0], cn[1], cn[2], cn[3]);
            __half2 hlo = __floats2half2_rn(hn[0], hn[1]);
            __half2 hhi = __floats2half2_rn(hn[2], hn[3]);
            uint2 hw;
            hw.x = *(unsigned*)&hlo;
            hw.y = *(unsigned*)&hhi;
            *(uint2*)(hout + eb * HID + ehcol) = hw;
            if (cell == 2)
                *(uint2*)(g_h2hist + (size_t)t * BATCH * HID + (size_t)eb * HID + ehcol) = hw;
        }
        // release ordering provided by grid_barrier (syncthreads + tid0 fence)
        grid_barrier();

        // next step's first chunk (needs fresh h; Gs already consumed)
        if (t + 1 < T_LEN) {
            Seg n0, n1; segs(t + 1, n0, n1);
            loadW(n0, n1, g, 0);
            loadA(n0, n1, g, 0);
            cp_commit();
        }
    }
}

// ---------------- final batched output GEMM: out = h2hist @ Wd^T + bd ----------------
__global__ void __launch_bounds__(128) k_out(const float* __restrict__ bd,
                                             float* __restrict__ out) {
    __shared__ __align__(16) unsigned char sraw[32256];
    __half (*As)[64][72] = reinterpret_cast<__half(*)[64][72]>(sraw);
    __half (*Ws)[48][72] = reinterpret_cast<__half(*)[48][72]>(sraw + 18432);
    float (*Gs)[52]      = reinterpret_cast<float(*)[52]>(sraw);

    int tid = threadIdx.x, warp = tid >> 5;
    int r0 = blockIdx.x * 64;
    int f0 = blockIdx.y * 48;

    const __half* A = g_h2hist + (size_t)r0 * HID;

    wmma::fragment<wmma::accumulator, 16, 16, 16, float> acc[3];
    #pragma unroll
    for (int c = 0; c < 3; c++) wmma::fill_fragment(acc[c], 0.f);

    auto load_chunk = [&](int i, int s) {
        int k0 = i * 64;
        #pragma unroll
        for (int p = 0; p < 4; p++) {
            int idx = p * 128 + tid;
            int r = idx >> 3, c8 = idx & 7;
            cp16(&As[s][r][c8 * 8], A + (size_t)r * HID + k0 + c8 * 8);
        }
        #pragma unroll
        for (int p = 0; p < 3; p++) {
            int idx = p * 128 + tid;
            int r = idx >> 3, c8 = idx & 7;
            cp16(&Ws[s][r][c8 * 8], g_Wdp + (size_t)(f0 + r) * HID + k0 + c8 * 8);
        }
        cp_commit();
    };

    const int nch = HID / 64;
    load_chunk(0, 0);
    for (int i = 0; i < nch; i++) {
        if (i + 1 < nch) { load_chunk(i + 1, (i + 1) & 1); cp_wait1(); }
        else             { cp_wait0(); }
        __syncthreads();
        int s = i & 1;
        #pragma unroll
        for (int kk = 0; kk < 4; kk++) {
            wmma::fragment<wmma::matrix_a, 16, 16, 16, __half, wmma::row_major> afr;
            wmma::load_matrix_sync(afr, &As[s][warp * 16][kk * 16], 72);
            #pragma unroll
            for (int c = 0; c < 3; c++) {
                wmma::fragment<wmma::matrix_b, 16, 16, 16, __half, wmma::col_major> bfr;
                wmma::load_matrix_sync(bfr, &Ws[s][c * 16][kk * 16], 72);
                wmma::mma_sync(acc[c], afr, bfr, acc[c]);
            }
        }
        __syncthreads();
    }

    #pragma unroll
    for (int c = 0; c < 3; c++)
        wmma::store_matrix_sync(&Gs[warp * 16][c * 16], acc[c], 52, wmma::mem_row_major);
    __syncthreads();

    for (int idx = tid; idx < 64 * 48; idx += 128) {
        int rr = idx / 48, cc = idx % 48;
        int f = f0 + cc;
        if (f >= F_IN) continue;
        int r = r0 + rr;
        int tt = r >> 6, b = r & 63;
        out[(size_t)b * (T_LEN * F_IN) + (size_t)tt * F_IN + f] = Gs[rr][cc] + bd[f];
    }
}

// ---------------- launch ----------------
extern "C" void kernel_launch(void* const* d_in, const int* in_sizes, int n_in,
                              void* d_out, int out_size) {
    (void)in_sizes; (void)n_in; (void)out_size;
    const float* real_seq = (const float*)d_in[0];
    const float* Wih1 = (const float*)d_in[1];
    const float* Whh1 = (const float*)d_in[2];
    const float* bih1 = (const float*)d_in[3];
    const float* bhh1 = (const float*)d_in[4];
    const float* Wih2 = (const float*)d_in[5];
    const float* Whh2 = (const float*)d_in[6];
    const float* bih2 = (const float*)d_in[7];
    const float* bhh2 = (const float*)d_in[8];
    const float* Wih3 = (const float*)d_in[9];
    const float* Whh3 = (const float*)d_in[10];
    const float* bih3 = (const float*)d_in[11];
    const float* bhh3 = (const float*)d_in[12];
    const float* Wd   = (const float*)d_in[13];
    const float* bd   = (const float*)d_in[14];
    float* out = (float*)d_out;

    cudaFuncSetAttribute(k_persist, cudaFuncAttributeMaxDynamicSharedMemorySize, SMEM_P);

    // launches 1-3: setup; launch 4 = k_persist (ncu capture slot)
    k_setup<<<8192, 256>>>(Whh1, Wih2, Whh2, Wih3, Whh3, Wih1, Wd, real_seq);
    k_w1d<<<dim3(16, 64), 256>>>(Wih1, Wd);
    k_bias<<<16, 256>>>(bih1, bhh1, bih2, bhh2, bih3, bhh3, Wih1, bd);

    // launch 4: the whole 512-step recurrence
    k_persist<<<N_BLOCKS, 512, SMEM_P>>>();

    // batched output projection
    dim3 og((T_LEN * BATCH) / 64, 3);
    k_out<<<og, 128>>>(bd, out);
}